// round 1
// baseline (speedup 1.0000x reference)
#include <cuda_runtime.h>
#include <math.h>

#define NN 6144
#define NV 3
#define NF 512
#define NK 10
#define KP 11
#define NITERS 2
#define BN_EPS 1e-5f

// ---------------- scratch (device globals, no allocation) ----------------
__device__ float g_proj[NV * NN * NK];
__device__ float g_Y[NV * NN * NK];
__device__ float g_h[NN * NK];
__device__ float g_z[NN * NK];
__device__ float g_stats[NITERS * 2 * NK]; // [t][sum|sumsq][k]

// ---------------- packed f32x2 helpers ----------------
__device__ __forceinline__ unsigned long long pack2(float a, float b) {
    unsigned long long r;
    asm("mov.b64 %0, {%1, %2};" : "=l"(r) : "f"(a), "f"(b));
    return r;
}
__device__ __forceinline__ void ffma2(unsigned long long& d, unsigned long long a, unsigned long long b) {
    asm("fma.rn.f32x2 %0, %1, %2, %0;" : "+l"(d) : "l"(a), "l"(b));
}
__device__ __forceinline__ float2 unpack2(unsigned long long v) {
    float2 r;
    asm("mov.b64 {%0, %1}, %2;" : "=f"(r.x), "=f"(r.y) : "l"(v));
    return r;
}

// ---------------- kernel 0: zero stats ----------------
__global__ void zero_stats_kernel() {
    int i = threadIdx.x;
    if (i < NITERS * 2 * NK) g_stats[i] = 0.0f;
}

// ---------------- kernel 1: proj[v,n,k] = sum_f X[v,n,f] U[v,f,k] ----------------
// 8 warps/block, one row per warp; U_v tile in smem (padded stride 11 -> conflict-free)
__global__ __launch_bounds__(256) void proj_kernel(const float* __restrict__ feat,
                                                   const float* __restrict__ U) {
    __shared__ float Us[NF * KP];
    int tid = threadIdx.x, lane = tid & 31, wid = tid >> 5;
    int bx = blockIdx.x;
    int v = bx / (NN / 8);
    int rb = bx % (NN / 8);

    for (int i = tid; i < NF * NK; i += 256)
        Us[(i / NK) * KP + (i % NK)] = U[(size_t)v * NF * NK + i];
    __syncthreads();

    int n = rb * 8 + wid;
    const float* xr = feat + ((size_t)v * NN + n) * NF;
    float acc[NK];
#pragma unroll
    for (int k = 0; k < NK; k++) acc[k] = 0.0f;

    for (int f = lane; f < NF; f += 32) {
        float x = xr[f];
        const float* ur = Us + f * KP;
#pragma unroll
        for (int k = 0; k < NK; k++) acc[k] = fmaf(x, ur[k], acc[k]);
    }
#pragma unroll
    for (int k = 0; k < NK; k++)
        for (int s = 16; s; s >>= 1) acc[k] += __shfl_xor_sync(0xffffffffu, acc[k], s);

    if (lane == 0) {
        float* pr = g_proj + ((size_t)v * NN + n) * NK;
#pragma unroll
        for (int k = 0; k < NK; k++) pr[k] = acc[k];
    }
}

// ---------------- kernel 2: Y[v,n,k] = sum_m L[v,n,m] * z[m,k] ----------------
// The HBM-bound workhorse. 8 warps * 4 rows = 32 rows/block, 576 blocks.
// z chunk (1024 rows, 11-pad) in smem; lanes stride m -> coalesced L, conflict-free LDS.
#define M_CHUNK 1024
#define GEMV_THREADS 256
#define RPW 4
#define ROWS_PER_BLOCK 32

__global__ __launch_bounds__(GEMV_THREADS) void gemv_kernel(const float* __restrict__ lap,
                                                            const float* __restrict__ z_ext,
                                                            int use_ext) {
    const float* zsrc = use_ext ? z_ext : g_z;
    __shared__ float zs[M_CHUNK * KP];

    int tid = threadIdx.x, lane = tid & 31, wid = tid >> 5;
    int bx = blockIdx.x;
    int v = bx / (NN / ROWS_PER_BLOCK);
    int rb = bx % (NN / ROWS_PER_BLOCK);
    int n0 = rb * ROWS_PER_BLOCK + wid * RPW;

    const float* Lbase = lap + ((size_t)v * NN + n0) * (size_t)NN;

    unsigned long long acc[RPW][5];
#pragma unroll
    for (int r = 0; r < RPW; r++)
#pragma unroll
        for (int p = 0; p < 5; p++) acc[r][p] = 0ull;

    for (int c = 0; c < NN; c += M_CHUNK) {
        __syncthreads();
        for (int i = tid; i < M_CHUNK * NK; i += GEMV_THREADS)
            zs[(i / NK) * KP + (i % NK)] = zsrc[c * NK + i];
        __syncthreads();

        const float* l0 = Lbase + c;
        const float* l1 = l0 + NN;
        const float* l2 = l0 + 2 * NN;
        const float* l3 = l0 + 3 * NN;

#pragma unroll 4
        for (int j = lane; j < M_CHUNK; j += 32) {
            float a0 = l0[j], a1 = l1[j], a2 = l2[j], a3 = l3[j];
            const float* zr = zs + j * KP;
            unsigned long long zp0 = pack2(zr[0], zr[1]);
            unsigned long long zp1 = pack2(zr[2], zr[3]);
            unsigned long long zp2 = pack2(zr[4], zr[5]);
            unsigned long long zp3 = pack2(zr[6], zr[7]);
            unsigned long long zp4 = pack2(zr[8], zr[9]);

            unsigned long long d0 = pack2(a0, a0);
            ffma2(acc[0][0], d0, zp0); ffma2(acc[0][1], d0, zp1); ffma2(acc[0][2], d0, zp2);
            ffma2(acc[0][3], d0, zp3); ffma2(acc[0][4], d0, zp4);
            unsigned long long d1 = pack2(a1, a1);
            ffma2(acc[1][0], d1, zp0); ffma2(acc[1][1], d1, zp1); ffma2(acc[1][2], d1, zp2);
            ffma2(acc[1][3], d1, zp3); ffma2(acc[1][4], d1, zp4);
            unsigned long long d2 = pack2(a2, a2);
            ffma2(acc[2][0], d2, zp0); ffma2(acc[2][1], d2, zp1); ffma2(acc[2][2], d2, zp2);
            ffma2(acc[2][3], d2, zp3); ffma2(acc[2][4], d2, zp4);
            unsigned long long d3 = pack2(a3, a3);
            ffma2(acc[3][0], d3, zp0); ffma2(acc[3][1], d3, zp1); ffma2(acc[3][2], d3, zp2);
            ffma2(acc[3][3], d3, zp3); ffma2(acc[3][4], d3, zp4);
        }
    }

#pragma unroll
    for (int r = 0; r < RPW; r++) {
        float vals[NK];
#pragma unroll
        for (int p = 0; p < 5; p++) {
            float2 f = unpack2(acc[r][p]);
            vals[2 * p] = f.x;
            vals[2 * p + 1] = f.y;
        }
#pragma unroll
        for (int k = 0; k < NK; k++)
            for (int s = 16; s; s >>= 1) vals[k] += __shfl_xor_sync(0xffffffffu, vals[k], s);
        if (lane == 0) {
            float* yr = g_Y + ((size_t)v * NN + n0 + r) * NK;
#pragma unroll
            for (int k = 0; k < NK; k++) yr[k] = vals[k];
        }
    }
}

// ---------------- kernel 3: softplus evidences + DS combine + BN stats ----------------
__device__ __forceinline__ float softplusf(float x) {
    return fmaxf(x, 0.0f) + log1pf(expf(-fabsf(x)));
}

__device__ __forceinline__ void ds_comb(float* a1, const float* a2) {
    float S1 = 0.0f, S2 = 0.0f;
#pragma unroll
    for (int k = 0; k < NK; k++) { S1 += a1[k]; S2 += a2[k]; }
    float i1 = 1.0f / S1, i2 = 1.0f / S2;
    float u1 = (float)NK * i1, u2 = (float)NK * i2;
    float b1[NK], b2[NK];
    float sb1 = 0.0f, sb2 = 0.0f, dot = 0.0f;
#pragma unroll
    for (int k = 0; k < NK; k++) {
        b1[k] = (a1[k] - 1.0f) * i1;
        b2[k] = (a2[k] - 1.0f) * i2;
        sb1 += b1[k];
        sb2 += b2[k];
        dot += b1[k] * b2[k];
    }
    float C = sb1 * sb2 - dot;
    float invd = 1.0f / (1.0f - C);
    // u = u1*u2*invd ;  S = K/u
    float Sn = (float)NK * (1.0f - C) / (u1 * u2);
#pragma unroll
    for (int k = 0; k < NK; k++)
        a1[k] = (b1[k] * b2[k] + b1[k] * u2 + b2[k] * u1) * invd * Sn + 1.0f;
}

__global__ __launch_bounds__(256) void combine_kernel(const float* __restrict__ z_ext,
                                                      int use_ext, int t) {
    const float* zsrc = use_ext ? z_ext : g_z;
    int n = blockIdx.x * 256 + threadIdx.x; // grid exactly covers N
    int lane = threadIdx.x & 31;

    float zn[NK];
#pragma unroll
    for (int k = 0; k < NK; k++) zn[k] = zsrc[n * NK + k];

    float ac[NK];
    {
        const float* yr = g_Y + (size_t)n * NK;
        const float* pr = g_proj + (size_t)n * NK;
#pragma unroll
        for (int k = 0; k < NK; k++) ac[k] = softplusf(zn[k] - yr[k] + pr[k]) + 1.0f;
    }
#pragma unroll
    for (int v = 1; v < NV; v++) {
        float av[NK];
        const float* yr = g_Y + ((size_t)v * NN + n) * NK;
        const float* pr = g_proj + ((size_t)v * NN + n) * NK;
#pragma unroll
        for (int k = 0; k < NK; k++) av[k] = softplusf(zn[k] - yr[k] + pr[k]) + 1.0f;
        ds_comb(ac, av);
    }

    float sq[NK];
#pragma unroll
    for (int k = 0; k < NK; k++) {
        g_h[n * NK + k] = ac[k];
        sq[k] = ac[k] * ac[k];
    }

    // warp reduce 20 values, then block-shared, then global atomics (20 per block)
#pragma unroll
    for (int k = 0; k < NK; k++) {
        for (int s = 16; s; s >>= 1) {
            ac[k] += __shfl_xor_sync(0xffffffffu, ac[k], s);
            sq[k] += __shfl_xor_sync(0xffffffffu, sq[k], s);
        }
    }
    __shared__ float sh[2 * NK];
    if (threadIdx.x < 2 * NK) sh[threadIdx.x] = 0.0f;
    __syncthreads();
    if (lane == 0) {
#pragma unroll
        for (int k = 0; k < NK; k++) {
            atomicAdd(&sh[k], ac[k]);
            atomicAdd(&sh[NK + k], sq[k]);
        }
    }
    __syncthreads();
    if (threadIdx.x < 2 * NK)
        atomicAdd(&g_stats[t * 2 * NK + threadIdx.x], sh[threadIdx.x]);
}

// ---------------- kernel 4: BatchNorm + SELU soft-threshold ----------------
__device__ __forceinline__ float seluf(float x) {
    const float sc = 1.0507009873554805f, al = 1.6732632423543772f;
    return x > 0.0f ? sc * x : sc * al * expm1f(x);
}

__global__ __launch_bounds__(256) void bn_selu_kernel(float* __restrict__ out,
                                                      const float* __restrict__ gamma,
                                                      const float* __restrict__ beta,
                                                      const float* __restrict__ theta,
                                                      int t) {
    int i = blockIdx.x * 256 + threadIdx.x; // grid exactly covers N*K
    int k = i % NK;
    float mu = g_stats[t * 2 * NK + k] * (1.0f / NN);
    float ms = g_stats[t * 2 * NK + NK + k] * (1.0f / NN);
    float var = ms - mu * mu;
    float inv = rsqrtf(var + BN_EPS);
    float hn = (g_h[i] - mu) * inv * gamma[k] + beta[k];
    float th = theta[0];
    float z = seluf(hn - th) - seluf(-hn - th);
    out[(size_t)t * NN * NK + i] = z;
    g_z[i] = z;
}

// ---------------- launcher ----------------
extern "C" void kernel_launch(void* const* d_in, const int* in_sizes, int n_in,
                              void* d_out, int out_size) {
    (void)in_sizes; (void)n_in; (void)out_size;
    const float* feat  = (const float*)d_in[0]; // [V,N,F]
    const float* lap   = (const float*)d_in[1]; // [V,N,N]
    const float* z0    = (const float*)d_in[2]; // [N,K]
    const float* U     = (const float*)d_in[3]; // [V,F,K]
    const float* theta = (const float*)d_in[4]; // [1]
    const float* gamma = (const float*)d_in[5]; // [K]
    const float* beta  = (const float*)d_in[6]; // [K]
    float* out = (float*)d_out;                 // [2,N,K]

    zero_stats_kernel<<<1, 64>>>();
    proj_kernel<<<NV * (NN / 8), 256>>>(feat, U);

    for (int t = 0; t < NITERS; t++) {
        int use_ext = (t == 0) ? 1 : 0;
        gemv_kernel<<<NV * (NN / ROWS_PER_BLOCK), GEMV_THREADS>>>(lap, z0, use_ext);
        combine_kernel<<<NN / 256, 256>>>(z0, use_ext, t);
        bn_selu_kernel<<<(NN * NK) / 256, 256>>>(out, gamma, beta, theta, t);
    }
}

// round 2
// speedup vs baseline: 2.3331x; 2.3331x over previous
#include <cuda_runtime.h>
#include <math.h>

#define NN 6144
#define NV 3
#define NF 512
#define NK 10
#define KP 11
#define NITERS 2
#define BN_EPS 1e-5f

// ---------------- scratch (device globals, no allocation) ----------------
__device__ float g_proj[NV * NN * NK];
__device__ float g_Y[NV * NN * NK];
__device__ float g_h[NN * NK];
__device__ float g_z[NN * NK];
__device__ float g_stats[NITERS * 2 * NK]; // [t][sum|sumsq][k]

// ---------------- packed f32x2 helpers ----------------
__device__ __forceinline__ unsigned long long pack2(float a, float b) {
    unsigned long long r;
    asm("mov.b64 %0, {%1, %2};" : "=l"(r) : "f"(a), "f"(b));
    return r;
}
__device__ __forceinline__ void ffma2(unsigned long long& d, unsigned long long a, unsigned long long b) {
    asm("fma.rn.f32x2 %0, %1, %2, %0;" : "+l"(d) : "l"(a), "l"(b));
}
__device__ __forceinline__ float2 unpack2(unsigned long long v) {
    float2 r;
    asm("mov.b64 {%0, %1}, %2;" : "=f"(r.x), "=f"(r.y) : "l"(v));
    return r;
}

// ---------------- kernel 0: zero stats ----------------
__global__ void zero_stats_kernel() {
    int i = threadIdx.x;
    if (i < NITERS * 2 * NK) g_stats[i] = 0.0f;
}

// ---------------- kernel 1: proj[v,n,k] = sum_f X[v,n,f] U[v,f,k] ----------------
// U transposed in smem (Ut[k][f]) -> float4 LDS conflict-free; float4 feature loads.
__global__ __launch_bounds__(256) void proj_kernel(const float* __restrict__ feat,
                                                   const float* __restrict__ U) {
    __shared__ float Ut[NK][NF];
    int tid = threadIdx.x, lane = tid & 31, wid = tid >> 5;
    int bx = blockIdx.x;
    int v = bx / (NN / 8);
    int rb = bx % (NN / 8);

    for (int i = tid; i < NF * NK; i += 256) {
        int f = i / NK, k = i % NK;
        Ut[k][f] = U[(size_t)v * NF * NK + i];
    }
    __syncthreads();

    int n = rb * 8 + wid;
    const float4* xr = (const float4*)(feat + ((size_t)v * NN + n) * NF);
    float acc[NK];
#pragma unroll
    for (int k = 0; k < NK; k++) acc[k] = 0.0f;

#pragma unroll
    for (int it = 0; it < NF / 128; it++) {
        int f4 = it * 32 + lane;          // float4 index
        float4 x = xr[f4];
#pragma unroll
        for (int k = 0; k < NK; k++) {
            float4 u = *(const float4*)&Ut[k][f4 * 4];
            acc[k] = fmaf(x.x, u.x, acc[k]);
            acc[k] = fmaf(x.y, u.y, acc[k]);
            acc[k] = fmaf(x.z, u.z, acc[k]);
            acc[k] = fmaf(x.w, u.w, acc[k]);
        }
    }
#pragma unroll
    for (int k = 0; k < NK; k++)
        for (int s = 16; s; s >>= 1) acc[k] += __shfl_xor_sync(0xffffffffu, acc[k], s);

    if (lane == 0) {
        float* pr = g_proj + ((size_t)v * NN + n) * NK;
#pragma unroll
        for (int k = 0; k < NK; k++) pr[k] = acc[k];
    }
}

// ---------------- kernel 2: Y[v,n,k] = sum_m L[v,n,m] * z[m,k] ----------------
// 512 threads (16 warps), 8 rows/warp -> 128 rows/block, grid = 144 = single wave.
// 16 LDG.32 in flight per warp (unroll 2), z tile in smem (11-pad, conflict-free).
#define M_CHUNK 1024
#define GEMV_THREADS 512
#define RPW 8
#define ROWS_PER_BLOCK 128   // 16 warps * 8 rows

__global__ __launch_bounds__(GEMV_THREADS, 1) void gemv_kernel(const float* __restrict__ lap,
                                                               const float* __restrict__ z_ext,
                                                               int use_ext) {
    const float* zsrc = use_ext ? z_ext : g_z;
    __shared__ float zs[M_CHUNK * KP];

    int tid = threadIdx.x, lane = tid & 31, wid = tid >> 5;
    int bx = blockIdx.x;
    int v = bx / (NN / ROWS_PER_BLOCK);
    int rb = bx % (NN / ROWS_PER_BLOCK);
    int n0 = rb * ROWS_PER_BLOCK + wid * RPW;

    const float* Lbase = lap + ((size_t)v * NN + n0) * (size_t)NN;

    unsigned long long acc[RPW][5];
#pragma unroll
    for (int r = 0; r < RPW; r++)
#pragma unroll
        for (int p = 0; p < 5; p++) acc[r][p] = 0ull;

    for (int c = 0; c < NN; c += M_CHUNK) {
        __syncthreads();
        for (int i = tid; i < M_CHUNK * NK; i += GEMV_THREADS)
            zs[(i / NK) * KP + (i % NK)] = zsrc[c * NK + i];
        __syncthreads();

        const float* l = Lbase + c;

#pragma unroll 2
        for (int j = lane; j < M_CHUNK; j += 32) {
            float a[RPW];
#pragma unroll
            for (int r = 0; r < RPW; r++) a[r] = l[r * NN + j];

            const float* zr = zs + j * KP;
            unsigned long long zp[5];
#pragma unroll
            for (int p = 0; p < 5; p++) zp[p] = pack2(zr[2 * p], zr[2 * p + 1]);

#pragma unroll
            for (int r = 0; r < RPW; r++) {
                unsigned long long d = pack2(a[r], a[r]);
#pragma unroll
                for (int p = 0; p < 5; p++) ffma2(acc[r][p], d, zp[p]);
            }
        }
    }

#pragma unroll
    for (int r = 0; r < RPW; r++) {
        float vals[NK];
#pragma unroll
        for (int p = 0; p < 5; p++) {
            float2 f = unpack2(acc[r][p]);
            vals[2 * p] = f.x;
            vals[2 * p + 1] = f.y;
        }
#pragma unroll
        for (int k = 0; k < NK; k++)
            for (int s = 16; s; s >>= 1) vals[k] += __shfl_xor_sync(0xffffffffu, vals[k], s);
        if (lane == 0) {
            float* yr = g_Y + ((size_t)v * NN + n0 + r) * NK;
#pragma unroll
            for (int k = 0; k < NK; k++) yr[k] = vals[k];
        }
    }
}

// ---------------- kernel 3: softplus evidences + DS combine + BN stats ----------------
__device__ __forceinline__ float softplusf(float x) {
    return fmaxf(x, 0.0f) + __logf(1.0f + __expf(-fabsf(x)));
}

__device__ __forceinline__ void ds_comb(float* a1, const float* a2) {
    float S1 = 0.0f, S2 = 0.0f;
#pragma unroll
    for (int k = 0; k < NK; k++) { S1 += a1[k]; S2 += a2[k]; }
    float i1 = 1.0f / S1, i2 = 1.0f / S2;
    float u1 = (float)NK * i1, u2 = (float)NK * i2;
    float b1[NK], b2[NK];
    float sb1 = 0.0f, sb2 = 0.0f, dot = 0.0f;
#pragma unroll
    for (int k = 0; k < NK; k++) {
        b1[k] = (a1[k] - 1.0f) * i1;
        b2[k] = (a2[k] - 1.0f) * i2;
        sb1 += b1[k];
        sb2 += b2[k];
        dot += b1[k] * b2[k];
    }
    float C = sb1 * sb2 - dot;
    float invd = 1.0f / (1.0f - C);
    float Sn = (float)NK * (1.0f - C) / (u1 * u2);
#pragma unroll
    for (int k = 0; k < NK; k++)
        a1[k] = (b1[k] * b2[k] + b1[k] * u2 + b2[k] * u1) * invd * Sn + 1.0f;
}

#define CMB_THREADS 128
__global__ __launch_bounds__(CMB_THREADS) void combine_kernel(const float* __restrict__ z_ext,
                                                              int use_ext, int t) {
    const float* zsrc = use_ext ? z_ext : g_z;
    int n = blockIdx.x * CMB_THREADS + threadIdx.x; // grid exactly covers N
    int lane = threadIdx.x & 31;

    float zn[NK];
#pragma unroll
    for (int k = 0; k < NK; k++) zn[k] = zsrc[n * NK + k];

    float ac[NK];
    {
        const float* yr = g_Y + (size_t)n * NK;
        const float* pr = g_proj + (size_t)n * NK;
#pragma unroll
        for (int k = 0; k < NK; k++) ac[k] = softplusf(zn[k] - yr[k] + pr[k]) + 1.0f;
    }
#pragma unroll
    for (int v = 1; v < NV; v++) {
        float av[NK];
        const float* yr = g_Y + ((size_t)v * NN + n) * NK;
        const float* pr = g_proj + ((size_t)v * NN + n) * NK;
#pragma unroll
        for (int k = 0; k < NK; k++) av[k] = softplusf(zn[k] - yr[k] + pr[k]) + 1.0f;
        ds_comb(ac, av);
    }

    float sq[NK];
#pragma unroll
    for (int k = 0; k < NK; k++) {
        g_h[n * NK + k] = ac[k];
        sq[k] = ac[k] * ac[k];
    }

#pragma unroll
    for (int k = 0; k < NK; k++) {
        for (int s = 16; s; s >>= 1) {
            ac[k] += __shfl_xor_sync(0xffffffffu, ac[k], s);
            sq[k] += __shfl_xor_sync(0xffffffffu, sq[k], s);
        }
    }
    __shared__ float sh[2 * NK];
    if (threadIdx.x < 2 * NK) sh[threadIdx.x] = 0.0f;
    __syncthreads();
    if (lane == 0) {
#pragma unroll
        for (int k = 0; k < NK; k++) {
            atomicAdd(&sh[k], ac[k]);
            atomicAdd(&sh[NK + k], sq[k]);
        }
    }
    __syncthreads();
    if (threadIdx.x < 2 * NK)
        atomicAdd(&g_stats[t * 2 * NK + threadIdx.x], sh[threadIdx.x]);
}

// ---------------- kernel 4: BatchNorm + SELU soft-threshold ----------------
__device__ __forceinline__ float seluf(float x) {
    const float sc = 1.0507009873554805f, al = 1.6732632423543772f;
    return x > 0.0f ? sc * x : sc * al * (__expf(x) - 1.0f);
}

__global__ __launch_bounds__(256) void bn_selu_kernel(float* __restrict__ out,
                                                      const float* __restrict__ gamma,
                                                      const float* __restrict__ beta,
                                                      const float* __restrict__ theta,
                                                      int t) {
    int i = blockIdx.x * 256 + threadIdx.x; // grid exactly covers N*K
    int k = i % NK;
    float mu = g_stats[t * 2 * NK + k] * (1.0f / NN);
    float ms = g_stats[t * 2 * NK + NK + k] * (1.0f / NN);
    float var = ms - mu * mu;
    float inv = rsqrtf(var + BN_EPS);
    float hn = (g_h[i] - mu) * inv * gamma[k] + beta[k];
    float th = theta[0];
    float z = seluf(hn - th) - seluf(-hn - th);
    out[(size_t)t * NN * NK + i] = z;
    g_z[i] = z;
}

// ---------------- launcher ----------------
extern "C" void kernel_launch(void* const* d_in, const int* in_sizes, int n_in,
                              void* d_out, int out_size) {
    (void)in_sizes; (void)n_in; (void)out_size;
    const float* feat  = (const float*)d_in[0]; // [V,N,F]
    const float* lap   = (const float*)d_in[1]; // [V,N,N]
    const float* z0    = (const float*)d_in[2]; // [N,K]
    const float* U     = (const float*)d_in[3]; // [V,F,K]
    const float* theta = (const float*)d_in[4]; // [1]
    const float* gamma = (const float*)d_in[5]; // [K]
    const float* beta  = (const float*)d_in[6]; // [K]
    float* out = (float*)d_out;                 // [2,N,K]

    zero_stats_kernel<<<1, 64>>>();
    proj_kernel<<<NV * (NN / 8), 256>>>(feat, U);

    for (int t = 0; t < NITERS; t++) {
        int use_ext = (t == 0) ? 1 : 0;
        gemv_kernel<<<NV * (NN / ROWS_PER_BLOCK), GEMV_THREADS>>>(lap, z0, use_ext);
        combine_kernel<<<NN / CMB_THREADS, CMB_THREADS>>>(z0, use_ext, t);
        bn_selu_kernel<<<(NN * NK) / 256, 256>>>(out, gamma, beta, theta, t);
    }
}